// round 4
// baseline (speedup 1.0000x reference)
#include <cuda_runtime.h>
#include <cuda_fp16.h>
#include <stdint.h>
#include <math.h>

// ---------------------------------------------------------------------------
// GCLSTM (K=1 ChebConv -> edge data unused). fp16 HMMA path with gate fusion.
//   GEMM1 (fused): Pint = [x|h] @ Wt^T + bias, gate-interleaved columns
//                  (col 4j+g); epilogue computes I,F,That,O -> h0, c0, R
//   GEMM2: out = R @ WlinT^T + b_lin
// Output tuple: [out | h0 | c0], each 50000*256 fp32.
// ---------------------------------------------------------------------------

#define NNODES 50000

__device__ __half g_R[(size_t)NNODES * 256];     // relu(h0) fp16
__device__ __half g_Wt[1024 * 512];              // GEMM1 B: [4j+g][k]
__device__ __half g_WlT[256 * 256];              // GEMM2 B: [n][k] = Wlin[k][n]
__device__ float  g_bias[1024];                  // (bth_g + b_g) interleaved

// ---------------------------------------------------------------------------
__device__ __forceinline__ uint32_t smem_u32(const void* p) {
    uint32_t a;
    asm("{ .reg .u64 t; cvta.to.shared.u64 t, %1; cvt.u32.u64 %0, t; }"
        : "=r"(a) : "l"(p));
    return a;
}
__device__ __forceinline__ void ldmA4(uint32_t* a, uint32_t addr) {
    asm volatile("ldmatrix.sync.aligned.m8n8.x4.shared.b16 {%0,%1,%2,%3}, [%4];"
        : "=r"(a[0]), "=r"(a[1]), "=r"(a[2]), "=r"(a[3]) : "r"(addr));
}
__device__ __forceinline__ void ldmB2(uint32_t* b, uint32_t addr) {
    asm volatile("ldmatrix.sync.aligned.m8n8.x2.shared.b16 {%0,%1}, [%2];"
        : "=r"(b[0]), "=r"(b[1]) : "r"(addr));
}
__device__ __forceinline__ void mma16816(float* d, const uint32_t* a, const uint32_t* b) {
    asm volatile(
        "mma.sync.aligned.m16n8k16.row.col.f32.f16.f16.f32 "
        "{%0,%1,%2,%3},{%4,%5,%6,%7},{%8,%9},{%0,%1,%2,%3};"
        : "+f"(d[0]), "+f"(d[1]), "+f"(d[2]), "+f"(d[3])
        : "r"(a[0]), "r"(a[1]), "r"(a[2]), "r"(a[3]), "r"(b[0]), "r"(b[1]));
}
__device__ __forceinline__ void cp16(uint32_t dst, const void* src) {
    asm volatile("cp.async.cg.shared.global [%0], [%1], 16;" :: "r"(dst), "l"(src));
}
__device__ __forceinline__ void cp_commit() {
    asm volatile("cp.async.commit_group;");
}
template <int N>
__device__ __forceinline__ void cp_wait() {
    asm volatile("cp.async.wait_group %0;" :: "n"(N));
}

__device__ __forceinline__ float sigf(float x)  { return 1.f / (1.f + __expf(-x)); }
__device__ __forceinline__ float tanf_(float x) { return 2.f / (1.f + __expf(-2.f * x)) - 1.f; }

// ---------------------------------------------------------------------------
// HMMA GEMM, BM=BN=128, BK=32, 8 warps (2m x 4n), warp tile 64x32.
// GATES=true : A = [x|h] fp32 (converted in-flight), fused GCLSTM epilogue.
// GATES=false: A = A16 fp16 [M,K], plain epilogue C = acc + bias.
// ---------------------------------------------------------------------------
#define ASTR 40            // halves per smem row (32 + 8 pad) = 80 B
#define BUFB (128 * ASTR * 2)   // 10240 B per buffer

template <bool GATES>
__global__ void __launch_bounds__(256, 2)
hmma_gemm(const float* __restrict__ Ax, const float* __restrict__ Ah,
          const __half* __restrict__ A16, const __half* __restrict__ B,
          float* __restrict__ C, const float* __restrict__ bias,
          int M, int Ntot, int K,
          const float* __restrict__ c_in,
          const float* __restrict__ wci, const float* __restrict__ wcf,
          const float* __restrict__ wco,
          float* __restrict__ hout, float* __restrict__ cout,
          __half* __restrict__ Rout)
{
    __shared__ __align__(16) char usm[2 * BUFB * 2];   // A(2 buf) + B(2 buf) / stage
    __shared__ float sbias[128];
    __shared__ float swci[32], swcf[32], swco[32];

    const int tid  = threadIdx.x;
    const int lane = tid & 31;
    const int wid  = tid >> 5;
    const int warpm = wid >> 2;
    const int warpn = wid & 3;
    const int m0 = blockIdx.y * 128;
    const int n0 = blockIdx.x * 128;

    const uint32_t asb = smem_u32(usm);
    const uint32_t bsb = asb + 2 * BUFB;

    for (int i = tid; i < 128; i += 256) sbias[i] = bias[n0 + i];
    if (GATES && tid < 32) {
        int j = (n0 >> 2) + tid;
        swci[tid] = wci[j]; swcf[tid] = wcf[j]; swco[tid] = wco[j];
    }

    float acc[4][4][4];
#pragma unroll
    for (int mt = 0; mt < 4; ++mt)
#pragma unroll
        for (int nt = 0; nt < 4; ++nt)
#pragma unroll
            for (int e = 0; e < 4; ++e) acc[mt][nt][e] = 0.f;

    const int nch = K >> 5;
    uint32_t arg[8];   // GATES A staging (fp32 -> fp16)

    auto fetchA = [&](int kc) {   // GATES only
        const float* src = (kc < 8) ? Ax : Ah;
        const int cb = (kc & 7) * 32;
#pragma unroll
        for (int q = 0; q < 4; ++q) {
            int u = tid + q * 256;
            int r = u >> 3, kq = u & 7;
            int gr = m0 + r;
            float4 f = make_float4(0.f, 0.f, 0.f, 0.f);
            if (gr < M)
                f = *(const float4*)(src + (size_t)gr * 256 + cb + kq * 4);
            __half2 h0 = __floats2half2_rn(f.x, f.y);
            __half2 h1 = __floats2half2_rn(f.z, f.w);
            arg[q * 2 + 0] = *(uint32_t*)&h0;
            arg[q * 2 + 1] = *(uint32_t*)&h1;
        }
    };
    auto storeA = [&](int buf) {   // GATES only
#pragma unroll
        for (int q = 0; q < 4; ++q) {
            int u = tid + q * 256;
            int r = u >> 3, kq = u & 7;
            *(uint2*)(usm + buf * BUFB + r * 80 + kq * 8) =
                make_uint2(arg[q * 2], arg[q * 2 + 1]);
        }
    };
    auto issueA16 = [&](int kc, int buf) {   // !GATES
#pragma unroll
        for (int q = 0; q < 2; ++q) {
            int u = tid + q * 256;
            int r = u >> 2, kq = u & 3;
            int gr = m0 + r;
            if (gr < M)
                cp16(asb + buf * BUFB + r * 80 + kq * 16,
                     A16 + (size_t)gr * K + kc * 32 + kq * 8);
        }
    };
    auto issueB = [&](int kc, int buf) {
#pragma unroll
        for (int q = 0; q < 2; ++q) {
            int u = tid + q * 256;
            int r = u >> 2, kq = u & 3;
            cp16(bsb + buf * BUFB + r * 80 + kq * 16,
                 B + (size_t)(n0 + r) * K + kc * 32 + kq * 8);
        }
    };

    // prologue: chunk 0 -> buf 0
    if (GATES) fetchA(0); else issueA16(0, 0);
    issueB(0, 0);
    cp_commit();
    if (GATES) storeA(0);

    const int mrow = warpm * 64 + (lane & 15);
    const int nrow = warpn * 32 + (lane & 7);
    const int aksel = (lane >> 4) * 8;
    const int bksel = ((lane >> 3) & 1) * 8;

    for (int t = 0; t < nch; ++t) {
        const int buf = t & 1;
        const bool pf = (t + 1 < nch);
        if (pf) {
            if (GATES) fetchA(t + 1); else issueA16(t + 1, buf ^ 1);
            issueB(t + 1, buf ^ 1);
            cp_commit();
            cp_wait<1>();
        } else {
            cp_wait<0>();
        }
        __syncthreads();

        const uint32_t abase = asb + buf * BUFB + mrow * 80;
        const uint32_t bbase = bsb + buf * BUFB + nrow * 80;
#pragma unroll
        for (int ks = 0; ks < 2; ++ks) {
            const int k0 = ks * 16;
            uint32_t afr[4][4], bfr[4][2];
#pragma unroll
            for (int mt = 0; mt < 4; ++mt)
                ldmA4(afr[mt], abase + mt * 16 * 80 + (k0 + aksel) * 2);
#pragma unroll
            for (int nt = 0; nt < 4; ++nt)
                ldmB2(bfr[nt], bbase + nt * 8 * 80 + (k0 + bksel) * 2);
#pragma unroll
            for (int mt = 0; mt < 4; ++mt)
#pragma unroll
                for (int nt = 0; nt < 4; ++nt)
                    mma16816(acc[mt][nt], afr[mt], bfr[nt]);
        }

        if (pf && GATES) storeA(buf ^ 1);
        __syncthreads();
    }

    if (GATES) {
        // ---- fused GCLSTM epilogue: stage via smem in two 64-row halves ----
        float* stage = (float*)usm;          // 64 x 132 fp32 = 33792 B (fits)
        const int jbase = n0 >> 2;
        for (int hf = 0; hf < 2; ++hf) {
            __syncthreads();
            if (warpm == hf) {
#pragma unroll
                for (int mt = 0; mt < 4; ++mt) {
                    int r0 = mt * 16 + (lane >> 2), r1 = r0 + 8;
#pragma unroll
                    for (int nt = 0; nt < 4; ++nt) {
                        int cl = warpn * 32 + nt * 8 + (lane & 3) * 2;
                        stage[r0 * 132 + cl]     = acc[mt][nt][0] + sbias[cl];
                        stage[r0 * 132 + cl + 1] = acc[mt][nt][1] + sbias[cl + 1];
                        stage[r1 * 132 + cl]     = acc[mt][nt][2] + sbias[cl];
                        stage[r1 * 132 + cl + 1] = acc[mt][nt][3] + sbias[cl + 1];
                    }
                }
            }
            __syncthreads();
#pragma unroll 1
            for (int rr = 0; rr < 8; ++rr) {
                int rl = wid * 8 + rr;
                int m = m0 + hf * 64 + rl;
                if (m < M) {
                    float4 p = *(float4*)&stage[rl * 132 + lane * 4];
                    size_t off = (size_t)m * 256 + jbase + lane;
                    float cv = c_in[off];
                    float I = sigf(p.x + swci[lane] * cv);
                    float F = sigf(p.y + swcf[lane] * cv);
                    float T = tanf_(p.z);
                    float Cn = F * cv + I * T;
                    float O = sigf(p.w + swco[lane] * Cn);
                    float H = O * tanf_(Cn);
                    hout[off] = H;
                    cout[off] = Cn;
                    Rout[off] = __float2half_rn(fmaxf(H, 0.f));
                }
            }
        }
    } else {
        // ---- plain epilogue ----
#pragma unroll
        for (int mt = 0; mt < 4; ++mt) {
            int r0 = m0 + warpm * 64 + mt * 16 + (lane >> 2);
            int r1 = r0 + 8;
#pragma unroll
            for (int nt = 0; nt < 4; ++nt) {
                int cl = warpn * 32 + nt * 8 + (lane & 3) * 2;
                int cg = n0 + cl;
                if (r0 < M) {
                    float2 v;
                    v.x = acc[mt][nt][0] + sbias[cl];
                    v.y = acc[mt][nt][1] + sbias[cl + 1];
                    *(float2*)(C + (size_t)r0 * Ntot + cg) = v;
                }
                if (r1 < M) {
                    float2 v;
                    v.x = acc[mt][nt][2] + sbias[cl];
                    v.y = acc[mt][nt][3] + sbias[cl + 1];
                    *(float2*)(C + (size_t)r1 * Ntot + cg) = v;
                }
            }
        }
    }
}

// ---------------------------------------------------------------------------
// Pack: g_Wt[4j+g][k] = (k<256 ? W_g[k][j] : Th_g[k-256][j]) fp16;
//       g_WlT[n][k] = Wlin[k][n]; g_bias[4j+g] = bth_g[j] + b_g[j].
// ---------------------------------------------------------------------------
__global__ void pack_kernel(
    const float* __restrict__ Wi, const float* __restrict__ Wf,
    const float* __restrict__ Wc, const float* __restrict__ Wo,
    const float* __restrict__ Ti, const float* __restrict__ Tf,
    const float* __restrict__ Tc, const float* __restrict__ To,
    const float* __restrict__ bthi, const float* __restrict__ bthf,
    const float* __restrict__ bthc, const float* __restrict__ btho,
    const float* __restrict__ bi, const float* __restrict__ bf,
    const float* __restrict__ bc, const float* __restrict__ bo,
    const float* __restrict__ Wlin)
{
    int idx = blockIdx.x * blockDim.x + threadIdx.x;
    if (idx < 524288) {                       // g_Wt
        int n = idx >> 9, k = idx & 511;
        int g = n & 3, j = n >> 2;
        float v;
        if (k < 256) {
            const float* W = (g == 0) ? Wi : (g == 1) ? Wf : (g == 2) ? Wc : Wo;
            v = W[k * 256 + j];
        } else {
            const float* T = (g == 0) ? Ti : (g == 1) ? Tf : (g == 2) ? Tc : To;
            v = T[(k - 256) * 256 + j];
        }
        g_Wt[idx] = __float2half_rn(v);
    } else if (idx < 524288 + 65536) {        // g_WlT
        int i2 = idx - 524288;
        int n = i2 >> 8, k = i2 & 255;
        g_WlT[i2] = __float2half_rn(Wlin[k * 256 + n]);
    } else if (idx < 524288 + 65536 + 1024) { // g_bias (interleaved)
        int n = idx - 524288 - 65536;
        int g = n & 3, j = n >> 2;
        const float* bth = (g == 0) ? bthi : (g == 1) ? bthf : (g == 2) ? bthc : btho;
        const float* bb  = (g == 0) ? bi   : (g == 1) ? bf   : (g == 2) ? bc   : bo;
        g_bias[n] = bth[j] + bb[j];
    }
}

// ---------------------------------------------------------------------------
extern "C" void kernel_launch(void* const* d_in, const int* in_sizes, int n_in,
                              void* d_out, int out_size)
{
    const float* x    = (const float*)d_in[0];
    // d_in[1] edge_index, d_in[2] edge_weight -> unused (K=1 ChebConv)
    const float* h    = (const float*)d_in[3];
    const float* c    = (const float*)d_in[4];
    const float* Wi   = (const float*)d_in[5];
    const float* Wf   = (const float*)d_in[6];
    const float* Wc   = (const float*)d_in[7];
    const float* Wo   = (const float*)d_in[8];
    const float* Ti   = (const float*)d_in[9];
    const float* Tf   = (const float*)d_in[10];
    const float* Tc   = (const float*)d_in[11];
    const float* To   = (const float*)d_in[12];
    const float* bthi = (const float*)d_in[13];
    const float* bthf = (const float*)d_in[14];
    const float* bthc = (const float*)d_in[15];
    const float* btho = (const float*)d_in[16];
    const float* wci  = (const float*)d_in[17];
    const float* wcf  = (const float*)d_in[18];
    const float* wco  = (const float*)d_in[19];
    const float* bi   = (const float*)d_in[20];
    const float* bf   = (const float*)d_in[21];
    const float* bc   = (const float*)d_in[22];
    const float* bo   = (const float*)d_in[23];
    const float* Wlin = (const float*)d_in[24];
    const float* blin = (const float*)d_in[25];
    float* out = (float*)d_out;

    float *pBias;
    __half *pWt, *pWlT, *pR;
    cudaGetSymbolAddress((void**)&pBias, g_bias);
    cudaGetSymbolAddress((void**)&pWt, g_Wt);
    cudaGetSymbolAddress((void**)&pWlT, g_WlT);
    cudaGetSymbolAddress((void**)&pR, g_R);

    // 1) pack weights/bias to fp16 (gate-interleaved)
    pack_kernel<<<(524288 + 65536 + 1024 + 255) / 256, 256>>>(
        Wi, Wf, Wc, Wo, Ti, Tf, Tc, To,
        bthi, bthf, bthc, btho, bi, bf, bc, bo, Wlin);

    const size_t elems = (size_t)NNODES * 256;

    // 2) GEMM1 (fused gates): writes h0, c0, R directly
    hmma_gemm<true><<<dim3(8, (NNODES + 127) / 128), 256>>>(
        x, h, nullptr, pWt, nullptr, pBias, NNODES, 1024, 512,
        c, wci, wcf, wco, out + elems, out + 2 * elems, pR);

    // 3) GEMM2: out = R @ WlinT^T + b_lin
    hmma_gemm<false><<<dim3(2, (NNODES + 127) / 128), 256>>>(
        nullptr, nullptr, pR, pWlT, out, blin, NNODES, 256, 256,
        nullptr, nullptr, nullptr, nullptr, nullptr, nullptr, nullptr);
}

// round 5
// speedup vs baseline: 1.2930x; 1.2930x over previous
#include <cuda_runtime.h>
#include <cuda_fp16.h>
#include <stdint.h>
#include <math.h>

// ---------------------------------------------------------------------------
// GCLSTM (K=1 ChebConv -> edge data unused). fp16 HMMA path.
//   prep : A16 = fp16([x | h])  [50000 x 512]
//   GEMM1: P(fp16) = A16 @ Wt^T + bias   (M=50000, N=1024, K=512)
//   gates: h0, c0 (fp32), R = relu(h0) (fp16)
//   GEMM2: out = R @ WlinT^T + b_lin     (M=50000, N=256,  K=256)
// Output tuple: [out | h0 | c0], each 50000*256 fp32.
// ---------------------------------------------------------------------------

#define NNODES 50000

__device__ __half g_A16[(size_t)NNODES * 512];   // [x|h] fp16
__device__ __half g_P[(size_t)NNODES * 1024];    // preactivations fp16
__device__ __half g_R[(size_t)NNODES * 256];     // relu(h0) fp16
__device__ __half g_Wt[1024 * 512];              // GEMM1 B: [n][k]
__device__ __half g_WlT[256 * 256];              // GEMM2 B: [n][k] = Wlin[k][n]
__device__ float  g_bias[1024];                  // bth_g + b_g

// ---------------------------------------------------------------------------
__device__ __forceinline__ uint32_t smem_u32(const void* p) {
    uint32_t a;
    asm("{ .reg .u64 t; cvta.to.shared.u64 t, %1; cvt.u32.u64 %0, t; }"
        : "=r"(a) : "l"(p));
    return a;
}
__device__ __forceinline__ void ldmA4(uint32_t* a, uint32_t addr) {
    asm volatile("ldmatrix.sync.aligned.m8n8.x4.shared.b16 {%0,%1,%2,%3}, [%4];"
        : "=r"(a[0]), "=r"(a[1]), "=r"(a[2]), "=r"(a[3]) : "r"(addr));
}
__device__ __forceinline__ void ldmB2(uint32_t* b, uint32_t addr) {
    asm volatile("ldmatrix.sync.aligned.m8n8.x2.shared.b16 {%0,%1}, [%2];"
        : "=r"(b[0]), "=r"(b[1]) : "r"(addr));
}
__device__ __forceinline__ void mma16816(float* d, const uint32_t* a, const uint32_t* b) {
    asm volatile(
        "mma.sync.aligned.m16n8k16.row.col.f32.f16.f16.f32 "
        "{%0,%1,%2,%3},{%4,%5,%6,%7},{%8,%9},{%0,%1,%2,%3};"
        : "+f"(d[0]), "+f"(d[1]), "+f"(d[2]), "+f"(d[3])
        : "r"(a[0]), "r"(a[1]), "r"(a[2]), "r"(a[3]), "r"(b[0]), "r"(b[1]));
}
__device__ __forceinline__ void cp16(uint32_t dst, const void* src) {
    asm volatile("cp.async.cg.shared.global [%0], [%1], 16;" :: "r"(dst), "l"(src));
}
__device__ __forceinline__ void cp_commit() { asm volatile("cp.async.commit_group;"); }
template <int N>
__device__ __forceinline__ void cp_wait() {
    asm volatile("cp.async.wait_group %0;" :: "n"(N));
}

__device__ __forceinline__ float sigf(float x)  { return 1.f / (1.f + __expf(-x)); }
__device__ __forceinline__ float tanf_(float x) { return 2.f / (1.f + __expf(-2.f * x)) - 1.f; }

// ---------------------------------------------------------------------------
// HMMA GEMM: BM=BN=128, BK=32, 8 warps (2m x 4n), warp tile 64x32.
// 3-stage cp.async pipeline. A fp16 [M,K], B fp16 [Ntot,K] (K contiguous).
// HALF_OUT: C is __half (P); else C fp32. Bias fused in both.
// ---------------------------------------------------------------------------
#define ASTR 40                   // halves per smem row (32 + 8 pad) = 80 B
#define TBYTES (128 * ASTR * 2)   // 10240 B per tile buffer
#define SMEM_DYN (6 * TBYTES)     // 3 stages x (A + B)

template <bool HALF_OUT>
__global__ void __launch_bounds__(256)
hmma_gemm(const __half* __restrict__ A16, const __half* __restrict__ B,
          void* __restrict__ Cv, const float* __restrict__ bias,
          int M, int Ntot, int K)
{
    extern __shared__ __align__(16) char usm[];
    __shared__ float sbias[128];

    const int tid  = threadIdx.x;
    const int lane = tid & 31;
    const int wid  = tid >> 5;
    const int warpm = wid >> 2;
    const int warpn = wid & 3;
    const int m0 = blockIdx.y * 128;
    const int n0 = blockIdx.x * 128;

    const uint32_t asb = smem_u32(usm);          // A: 3 x TBYTES
    const uint32_t bsb = asb + 3 * TBYTES;       // B: 3 x TBYTES

    for (int i = tid; i < 128; i += 256) sbias[i] = bias[n0 + i];

    float acc[4][4][4];
#pragma unroll
    for (int mt = 0; mt < 4; ++mt)
#pragma unroll
        for (int nt = 0; nt < 4; ++nt)
#pragma unroll
            for (int e = 0; e < 4; ++e) acc[mt][nt][e] = 0.f;

    const int nch = K >> 5;

    auto issue = [&](int kc, int st) {
        // A tile: 128 rows x 32 halves
#pragma unroll
        for (int q = 0; q < 2; ++q) {
            int u = tid + q * 256;
            int r = u >> 2, kq = u & 3;
            int gr = m0 + r;
            if (gr < M)
                cp16(asb + st * TBYTES + r * 80 + kq * 16,
                     A16 + (size_t)gr * K + kc * 32 + kq * 8);
        }
        // B tile: 128 rows x 32 halves
#pragma unroll
        for (int q = 0; q < 2; ++q) {
            int u = tid + q * 256;
            int r = u >> 2, kq = u & 3;
            cp16(bsb + st * TBYTES + r * 80 + kq * 16,
                 B + (size_t)(n0 + r) * K + kc * 32 + kq * 8);
        }
    };

    // prologue: stages 0,1
    issue(0, 0); cp_commit();
    issue(1, 1); cp_commit();

    const int mrow = warpm * 64 + (lane & 15);
    const int nrow = warpn * 32 + (lane & 7);
    const int aksel = (lane >> 4) * 8;
    const int bksel = ((lane >> 3) & 1) * 8;

    for (int t = 0; t < nch; ++t) {
        if (t + 2 < nch) issue(t + 2, (t + 2) % 3);
        cp_commit();               // empty groups near the tail keep count uniform
        cp_wait<2>();              // group t complete
        __syncthreads();

        const int st = t % 3;
        const uint32_t abase = asb + st * TBYTES + mrow * 80;
        const uint32_t bbase = bsb + st * TBYTES + nrow * 80;
#pragma unroll
        for (int ks = 0; ks < 2; ++ks) {
            const int k0 = ks * 16;
            uint32_t afr[4][4], bfr[4][2];
#pragma unroll
            for (int mt = 0; mt < 4; ++mt)
                ldmA4(afr[mt], abase + mt * 16 * 80 + (k0 + aksel) * 2);
#pragma unroll
            for (int nt = 0; nt < 4; ++nt)
                ldmB2(bfr[nt], bbase + nt * 8 * 80 + (k0 + bksel) * 2);
#pragma unroll
            for (int mt = 0; mt < 4; ++mt)
#pragma unroll
                for (int nt = 0; nt < 4; ++nt)
                    mma16816(acc[mt][nt], afr[mt], bfr[nt]);
        }
        __syncthreads();
    }

    // ---- epilogue ----
#pragma unroll
    for (int mt = 0; mt < 4; ++mt) {
        int r0 = m0 + warpm * 64 + mt * 16 + (lane >> 2);
        int r1 = r0 + 8;
#pragma unroll
        for (int nt = 0; nt < 4; ++nt) {
            int cl = warpn * 32 + nt * 8 + (lane & 3) * 2;
            int cg = n0 + cl;
            float b0 = sbias[cl], b1 = sbias[cl + 1];
            if (HALF_OUT) {
                __half* C = (__half*)Cv;
                if (r0 < M) {
                    __half2 v = __floats2half2_rn(acc[mt][nt][0] + b0,
                                                  acc[mt][nt][1] + b1);
                    *(__half2*)(C + (size_t)r0 * Ntot + cg) = v;
                }
                if (r1 < M) {
                    __half2 v = __floats2half2_rn(acc[mt][nt][2] + b0,
                                                  acc[mt][nt][3] + b1);
                    *(__half2*)(C + (size_t)r1 * Ntot + cg) = v;
                }
            } else {
                float* C = (float*)Cv;
                if (r0 < M) {
                    float2 v = make_float2(acc[mt][nt][0] + b0, acc[mt][nt][1] + b1);
                    *(float2*)(C + (size_t)r0 * Ntot + cg) = v;
                }
                if (r1 < M) {
                    float2 v = make_float2(acc[mt][nt][2] + b0, acc[mt][nt][3] + b1);
                    *(float2*)(C + (size_t)r1 * Ntot + cg) = v;
                }
            }
        }
    }
}

// ---------------------------------------------------------------------------
// prep: A16[n][k] = fp16(k < 256 ? x[n][k] : h[n][k-256]); 8 halves/thread.
// ---------------------------------------------------------------------------
__global__ void prep_a16(const float* __restrict__ x, const float* __restrict__ h)
{
    int u = blockIdx.x * blockDim.x + threadIdx.x;     // NNODES*64 threads
    if (u >= NNODES * 64) return;
    int n = u >> 6;
    int kq = (u & 63) << 3;                            // 0..504 step 8
    const float* src = (kq < 256) ? (x + (size_t)n * 256 + kq)
                                  : (h + (size_t)n * 256 + kq - 256);
    float4 f0 = *(const float4*)(src);
    float4 f1 = *(const float4*)(src + 4);
    __half2 h0 = __floats2half2_rn(f0.x, f0.y);
    __half2 h1 = __floats2half2_rn(f0.z, f0.w);
    __half2 h2 = __floats2half2_rn(f1.x, f1.y);
    __half2 h3 = __floats2half2_rn(f1.z, f1.w);
    uint4 v;
    v.x = *(uint32_t*)&h0; v.y = *(uint32_t*)&h1;
    v.z = *(uint32_t*)&h2; v.w = *(uint32_t*)&h3;
    *(uint4*)(g_A16 + (size_t)n * 512 + kq) = v;
}

// ---------------------------------------------------------------------------
__global__ void pack_kernel(
    const float* __restrict__ Wi, const float* __restrict__ Wf,
    const float* __restrict__ Wc, const float* __restrict__ Wo,
    const float* __restrict__ Ti, const float* __restrict__ Tf,
    const float* __restrict__ Tc, const float* __restrict__ To,
    const float* __restrict__ bthi, const float* __restrict__ bthf,
    const float* __restrict__ bthc, const float* __restrict__ btho,
    const float* __restrict__ bi, const float* __restrict__ bf,
    const float* __restrict__ bc, const float* __restrict__ bo,
    const float* __restrict__ Wlin)
{
    int idx = blockIdx.x * blockDim.x + threadIdx.x;
    if (idx < 524288) {                       // g_Wt[n][k] = Wall[k][n]
        int n = idx >> 9, k = idx & 511;
        int g = n >> 8, jj = n & 255;
        float v;
        if (k < 256) {
            const float* W = (g == 0) ? Wi : (g == 1) ? Wf : (g == 2) ? Wc : Wo;
            v = W[k * 256 + jj];
        } else {
            const float* T = (g == 0) ? Ti : (g == 1) ? Tf : (g == 2) ? Tc : To;
            v = T[(k - 256) * 256 + jj];
        }
        g_Wt[idx] = __float2half_rn(v);
    } else if (idx < 524288 + 65536) {        // g_WlT[n][k] = Wlin[k][n]
        int i2 = idx - 524288;
        int n = i2 >> 8, k = i2 & 255;
        g_WlT[i2] = __float2half_rn(Wlin[k * 256 + n]);
    } else if (idx < 524288 + 65536 + 1024) { // g_bias
        int j = idx - 524288 - 65536;
        int g = j >> 8, jj = j & 255;
        const float* bth = (g == 0) ? bthi : (g == 1) ? bthf : (g == 2) ? bthc : btho;
        const float* bb  = (g == 0) ? bi   : (g == 1) ? bf   : (g == 2) ? bc   : bo;
        g_bias[j] = bth[jj] + bb[jj];
    }
}

// ---------------------------------------------------------------------------
// Gates from fp16 P: h0, c0 (fp32) + R (fp16). 4 columns per thread.
// ---------------------------------------------------------------------------
__global__ void gates_kernel(const float* __restrict__ c_in,
                             const float* __restrict__ wci,
                             const float* __restrict__ wcf,
                             const float* __restrict__ wco,
                             float* __restrict__ h_out,
                             float* __restrict__ c_out)
{
    int idx = blockIdx.x * blockDim.x + threadIdx.x;   // NNODES*64
    if (idx >= NNODES * 64) return;
    int n = idx >> 6;
    int j = (idx & 63) << 2;
    const __half* P = g_P + (size_t)n * 1024;

    __half2 pi01 = *(const __half2*)(P + j);
    __half2 pi23 = *(const __half2*)(P + j + 2);
    __half2 pf01 = *(const __half2*)(P + 256 + j);
    __half2 pf23 = *(const __half2*)(P + 256 + j + 2);
    __half2 pc01 = *(const __half2*)(P + 512 + j);
    __half2 pc23 = *(const __half2*)(P + 512 + j + 2);
    __half2 po01 = *(const __half2*)(P + 768 + j);
    __half2 po23 = *(const __half2*)(P + 768 + j + 2);

    float pi[4], pf[4], pc[4], po[4];
    { float2 t = __half22float2(pi01); pi[0] = t.x; pi[1] = t.y; }
    { float2 t = __half22float2(pi23); pi[2] = t.x; pi[3] = t.y; }
    { float2 t = __half22float2(pf01); pf[0] = t.x; pf[1] = t.y; }
    { float2 t = __half22float2(pf23); pf[2] = t.x; pf[3] = t.y; }
    { float2 t = __half22float2(pc01); pc[0] = t.x; pc[1] = t.y; }
    { float2 t = __half22float2(pc23); pc[2] = t.x; pc[3] = t.y; }
    { float2 t = __half22float2(po01); po[0] = t.x; po[1] = t.y; }
    { float2 t = __half22float2(po23); po[2] = t.x; po[3] = t.y; }

    float4 cv = *(const float4*)(c_in + (size_t)n * 256 + j);
    float4 wi = *(const float4*)(wci + j);
    float4 wf = *(const float4*)(wcf + j);
    float4 wo = *(const float4*)(wco + j);
    float cva[4] = {cv.x, cv.y, cv.z, cv.w};
    float wia[4] = {wi.x, wi.y, wi.z, wi.w};
    float wfa[4] = {wf.x, wf.y, wf.z, wf.w};
    float woa[4] = {wo.x, wo.y, wo.z, wo.w};

    float H[4], Cn[4];
#pragma unroll
    for (int e = 0; e < 4; ++e) {
        float I = sigf(pi[e] + wia[e] * cva[e]);
        float F = sigf(pf[e] + wfa[e] * cva[e]);
        float T = tanf_(pc[e]);
        Cn[e] = F * cva[e] + I * T;
        float O = sigf(po[e] + woa[e] * Cn[e]);
        H[e] = O * tanf_(Cn[e]);
    }

    size_t off = (size_t)n * 256 + j;
    *(float4*)(h_out + off) = make_float4(H[0], H[1], H[2], H[3]);
    *(float4*)(c_out + off) = make_float4(Cn[0], Cn[1], Cn[2], Cn[3]);

    __half2 r01 = __floats2half2_rn(fmaxf(H[0], 0.f), fmaxf(H[1], 0.f));
    __half2 r23 = __floats2half2_rn(fmaxf(H[2], 0.f), fmaxf(H[3], 0.f));
    uint2 rv;
    rv.x = *(uint32_t*)&r01;
    rv.y = *(uint32_t*)&r23;
    *(uint2*)(g_R + off) = rv;
}

// ---------------------------------------------------------------------------
extern "C" void kernel_launch(void* const* d_in, const int* in_sizes, int n_in,
                              void* d_out, int out_size)
{
    const float* x    = (const float*)d_in[0];
    // d_in[1] edge_index, d_in[2] edge_weight -> unused (K=1 ChebConv)
    const float* h    = (const float*)d_in[3];
    const float* c    = (const float*)d_in[4];
    const float* Wi   = (const float*)d_in[5];
    const float* Wf   = (const float*)d_in[6];
    const float* Wc   = (const float*)d_in[7];
    const float* Wo   = (const float*)d_in[8];
    const float* Ti   = (const float*)d_in[9];
    const float* Tf   = (const float*)d_in[10];
    const float* Tc   = (const float*)d_in[11];
    const float* To   = (const float*)d_in[12];
    const float* bthi = (const float*)d_in[13];
    const float* bthf = (const float*)d_in[14];
    const float* bthc = (const float*)d_in[15];
    const float* btho = (const float*)d_in[16];
    const float* wci  = (const float*)d_in[17];
    const float* wcf  = (const float*)d_in[18];
    const float* wco  = (const float*)d_in[19];
    const float* bi   = (const float*)d_in[20];
    const float* bf   = (const float*)d_in[21];
    const float* bc   = (const float*)d_in[22];
    const float* bo   = (const float*)d_in[23];
    const float* Wlin = (const float*)d_in[24];
    const float* blin = (const float*)d_in[25];
    float* out = (float*)d_out;

    float *pBias;
    __half *pA16, *pP, *pWt, *pWlT, *pR;
    cudaGetSymbolAddress((void**)&pBias, g_bias);
    cudaGetSymbolAddress((void**)&pA16, g_A16);
    cudaGetSymbolAddress((void**)&pP, g_P);
    cudaGetSymbolAddress((void**)&pWt, g_Wt);
    cudaGetSymbolAddress((void**)&pWlT, g_WlT);
    cudaGetSymbolAddress((void**)&pR, g_R);

    cudaFuncSetAttribute(hmma_gemm<true>,
                         cudaFuncAttributeMaxDynamicSharedMemorySize, SMEM_DYN);
    cudaFuncSetAttribute(hmma_gemm<false>,
                         cudaFuncAttributeMaxDynamicSharedMemorySize, SMEM_DYN);

    // 1) pack weights/bias to fp16
    pack_kernel<<<(524288 + 65536 + 1024 + 255) / 256, 256>>>(
        Wi, Wf, Wc, Wo, Ti, Tf, Tc, To,
        bthi, bthf, bthc, btho, bi, bf, bc, bo, Wlin);

    // 2) A16 = fp16([x|h])
    prep_a16<<<(NNODES * 64 + 255) / 256, 256>>>(x, h);

    // 3) GEMM1: P = A16 @ Wt^T + bias  (fp16 out)
    hmma_gemm<true><<<dim3(8, (NNODES + 127) / 128), 256, SMEM_DYN>>>(
        pA16, pWt, pP, pBias, NNODES, 1024, 512);

    // 4) gates -> h0, c0, R
    const size_t elems = (size_t)NNODES * 256;
    gates_kernel<<<(NNODES * 64 + 255) / 256, 256>>>(
        c, wci, wcf, wco, out + elems, out + 2 * elems);

    // 5) GEMM2: out = R @ WlinT^T + b_lin  (fp32 out)
    hmma_gemm<false><<<dim3(2, (NNODES + 127) / 128), 256, SMEM_DYN>>>(
        pR, pWlT, out, blin, NNODES, 256, 256);
}

// round 6
// speedup vs baseline: 1.2958x; 1.0022x over previous
#include <cuda_runtime.h>
#include <cuda_fp16.h>
#include <stdint.h>
#include <math.h>

// ---------------------------------------------------------------------------
// GCLSTM (K=1 ChebConv -> edge data unused). fp16 HMMA path.
//   prep : A16 = fp16([x | h])  [50000 x 512]
//   GEMM1: P(fp16) = A16 @ Wt^T + bias   (M=50000, N=1024, K=512)
//   gates: h0, c0 (fp32), R = relu(h0) (fp16)
//   GEMM2: out = R @ WlinT^T + b_lin     (M=50000, N=256,  K=256)
// GEMM config: CTA 128x256, warp 64x64 (8 warps), BK=32, 4-stage cp.async,
// single __syncthreads per K-iter.
// Output tuple: [out | h0 | c0], each 50000*256 fp32.
// ---------------------------------------------------------------------------

#define NNODES 50000

__device__ __half g_A16[(size_t)NNODES * 512];
__device__ __half g_P[(size_t)NNODES * 1024];
__device__ __half g_R[(size_t)NNODES * 256];
__device__ __half g_Wt[1024 * 512];
__device__ __half g_WlT[256 * 256];
__device__ float  g_bias[1024];

// ---------------------------------------------------------------------------
__device__ __forceinline__ uint32_t smem_u32(const void* p) {
    uint32_t a;
    asm("{ .reg .u64 t; cvta.to.shared.u64 t, %1; cvt.u32.u64 %0, t; }"
        : "=r"(a) : "l"(p));
    return a;
}
__device__ __forceinline__ void ldm4(uint32_t* a, uint32_t addr) {
    asm volatile("ldmatrix.sync.aligned.m8n8.x4.shared.b16 {%0,%1,%2,%3}, [%4];"
        : "=r"(a[0]), "=r"(a[1]), "=r"(a[2]), "=r"(a[3]) : "r"(addr));
}
__device__ __forceinline__ void mma16816(float* d, const uint32_t* a, const uint32_t* b) {
    asm volatile(
        "mma.sync.aligned.m16n8k16.row.col.f32.f16.f16.f32 "
        "{%0,%1,%2,%3},{%4,%5,%6,%7},{%8,%9},{%0,%1,%2,%3};"
        : "+f"(d[0]), "+f"(d[1]), "+f"(d[2]), "+f"(d[3])
        : "r"(a[0]), "r"(a[1]), "r"(a[2]), "r"(a[3]), "r"(b[0]), "r"(b[1]));
}
__device__ __forceinline__ void cp16(uint32_t dst, const void* src) {
    asm volatile("cp.async.cg.shared.global [%0], [%1], 16;" :: "r"(dst), "l"(src));
}
__device__ __forceinline__ void cp_commit() { asm volatile("cp.async.commit_group;"); }
template <int N>
__device__ __forceinline__ void cp_wait() {
    asm volatile("cp.async.wait_group %0;" :: "n"(N));
}

__device__ __forceinline__ float sigf(float x)  { return 1.f / (1.f + __expf(-x)); }
__device__ __forceinline__ float tanf_(float x) { return 2.f / (1.f + __expf(-2.f * x)) - 1.f; }

// ---------------------------------------------------------------------------
// HMMA GEMM: BM=128, BN=256, BK=32, 8 warps (2m x 4n), warp tile 64x64.
// A fp16 [M,K], B fp16 [Ntot,K], C = A @ B^T + bias. 4-stage pipeline.
// ---------------------------------------------------------------------------
#define ABUF (128 * 80)            // 10240 B per A stage (80 B padded rows)
#define BBUF (256 * 80)            // 20480 B per B stage
#define STG  (ABUF + BBUF)         // 30720 B per stage
#define SMEM_DYN (4 * STG)         // 122880 B

template <bool HALF_OUT>
__global__ void __launch_bounds__(256, 1)
hmma_gemm(const __half* __restrict__ A16, const __half* __restrict__ B,
          void* __restrict__ Cv, const float* __restrict__ bias,
          int M, int Ntot, int K)
{
    extern __shared__ __align__(16) char usm[];
    __shared__ float sbias[256];

    const int tid  = threadIdx.x;
    const int lane = tid & 31;
    const int wid  = tid >> 5;
    const int warpm = wid >> 2;          // 0..1
    const int warpn = wid & 3;           // 0..3
    const int m0 = blockIdx.y * 128;
    const int n0 = blockIdx.x * 256;

    const uint32_t smb = smem_u32(usm);

    sbias[tid] = bias[n0 + tid];

    float acc[4][8][4];
#pragma unroll
    for (int mt = 0; mt < 4; ++mt)
#pragma unroll
        for (int nt = 0; nt < 8; ++nt)
#pragma unroll
            for (int e = 0; e < 4; ++e) acc[mt][nt][e] = 0.f;

    const int nch = K >> 5;

    auto issue = [&](int kc, int st) {
        const uint32_t ab = smb + st * STG;
        const uint32_t bb = ab + ABUF;
        // A: 128 rows x 32 halves = 512 cp16 -> 2/thread
#pragma unroll
        for (int q = 0; q < 2; ++q) {
            int u = tid + q * 256;
            int r = u >> 2, kq = u & 3;
            int gr = m0 + r;
            if (gr < M)
                cp16(ab + r * 80 + kq * 16,
                     A16 + (size_t)gr * K + kc * 32 + kq * 8);
        }
        // B: 256 rows x 32 halves = 1024 cp16 -> 4/thread
#pragma unroll
        for (int q = 0; q < 4; ++q) {
            int u = tid + q * 256;
            int r = u >> 2, kq = u & 3;
            cp16(bb + r * 80 + kq * 16,
                 B + (size_t)(n0 + r) * K + kc * 32 + kq * 8);
        }
    };

    // prologue: stages 0..2
    issue(0, 0); cp_commit();
    issue(1, 1); cp_commit();
    issue(2, 2); cp_commit();
    cp_wait<2>();
    __syncthreads();

    // ldmatrix lane addressing
    const int arow = warpm * 64 + (lane & 15);          // A: 16 rows / x4
    const int aoff = (lane >> 4) * 8;                   // k 0 / 8
    const int brow = warpn * 64 + ((lane >> 4) << 3) + (lane & 7);  // B: 16 rows / x4
    const int boff = ((lane >> 3) & 1) * 8;             // k 0 / 8

    for (int t = 0; t < nch; ++t) {
        if (t + 3 < nch) issue(t + 3, (t + 3) & 3);
        cp_commit();

        const int st = t & 3;
        const uint32_t ab = smb + st * STG + arow * 80;
        const uint32_t bb = smb + st * STG + ABUF + brow * 80;
#pragma unroll
        for (int ks = 0; ks < 2; ++ks) {
            const int k0 = ks * 16;
            uint32_t afr[4][4], bfr[8][2];
#pragma unroll
            for (int mt = 0; mt < 4; ++mt)
                ldm4(afr[mt], ab + mt * 16 * 80 + (k0 + aoff) * 2);
#pragma unroll
            for (int np = 0; np < 4; ++np) {
                uint32_t f[4];
                ldm4(f, bb + np * 16 * 80 + (k0 + boff) * 2);
                bfr[np * 2][0] = f[0]; bfr[np * 2][1] = f[1];
                bfr[np * 2 + 1][0] = f[2]; bfr[np * 2 + 1][1] = f[3];
            }
#pragma unroll
            for (int mt = 0; mt < 4; ++mt)
#pragma unroll
                for (int nt = 0; nt < 8; ++nt)
                    mma16816(acc[mt][nt], afr[mt], bfr[nt]);
        }

        cp_wait<2>();
        __syncthreads();
    }

    // ---- epilogue ----
#pragma unroll
    for (int mt = 0; mt < 4; ++mt) {
        int r0 = m0 + warpm * 64 + mt * 16 + (lane >> 2);
        int r1 = r0 + 8;
#pragma unroll
        for (int nt = 0; nt < 8; ++nt) {
            int cl = warpn * 64 + nt * 8 + (lane & 3) * 2;
            int cg = n0 + cl;
            float b0 = sbias[cl], b1 = sbias[cl + 1];
            if (HALF_OUT) {
                __half* C = (__half*)Cv;
                if (r0 < M)
                    *(__half2*)(C + (size_t)r0 * Ntot + cg) =
                        __floats2half2_rn(acc[mt][nt][0] + b0, acc[mt][nt][1] + b1);
                if (r1 < M)
                    *(__half2*)(C + (size_t)r1 * Ntot + cg) =
                        __floats2half2_rn(acc[mt][nt][2] + b0, acc[mt][nt][3] + b1);
            } else {
                float* C = (float*)Cv;
                if (r0 < M)
                    *(float2*)(C + (size_t)r0 * Ntot + cg) =
                        make_float2(acc[mt][nt][0] + b0, acc[mt][nt][1] + b1);
                if (r1 < M)
                    *(float2*)(C + (size_t)r1 * Ntot + cg) =
                        make_float2(acc[mt][nt][2] + b0, acc[mt][nt][3] + b1);
            }
        }
    }
}

// ---------------------------------------------------------------------------
__global__ void prep_a16(const float* __restrict__ x, const float* __restrict__ h)
{
    int u = blockIdx.x * blockDim.x + threadIdx.x;     // NNODES*64 threads
    if (u >= NNODES * 64) return;
    int n = u >> 6;
    int kq = (u & 63) << 3;
    const float* src = (kq < 256) ? (x + (size_t)n * 256 + kq)
                                  : (h + (size_t)n * 256 + kq - 256);
    float4 f0 = *(const float4*)(src);
    float4 f1 = *(const float4*)(src + 4);
    __half2 h0 = __floats2half2_rn(f0.x, f0.y);
    __half2 h1 = __floats2half2_rn(f0.z, f0.w);
    __half2 h2 = __floats2half2_rn(f1.x, f1.y);
    __half2 h3 = __floats2half2_rn(f1.z, f1.w);
    uint4 v;
    v.x = *(uint32_t*)&h0; v.y = *(uint32_t*)&h1;
    v.z = *(uint32_t*)&h2; v.w = *(uint32_t*)&h3;
    *(uint4*)(g_A16 + (size_t)n * 512 + kq) = v;
}

// ---------------------------------------------------------------------------
__global__ void pack_kernel(
    const float* __restrict__ Wi, const float* __restrict__ Wf,
    const float* __restrict__ Wc, const float* __restrict__ Wo,
    const float* __restrict__ Ti, const float* __restrict__ Tf,
    const float* __restrict__ Tc, const float* __restrict__ To,
    const float* __restrict__ bthi, const float* __restrict__ bthf,
    const float* __restrict__ bthc, const float* __restrict__ btho,
    const float* __restrict__ bi, const float* __restrict__ bf,
    const float* __restrict__ bc, const float* __restrict__ bo,
    const float* __restrict__ Wlin)
{
    int idx = blockIdx.x * blockDim.x + threadIdx.x;
    if (idx < 524288) {                       // g_Wt[n][k] = Wall[k][n]
        int n = idx >> 9, k = idx & 511;
        int g = n >> 8, jj = n & 255;
        float v;
        if (k < 256) {
            const float* W = (g == 0) ? Wi : (g == 1) ? Wf : (g == 2) ? Wc : Wo;
            v = W[k * 256 + jj];
        } else {
            const float* T = (g == 0) ? Ti : (g == 1) ? Tf : (g == 2) ? Tc : To;
            v = T[(k - 256) * 256 + jj];
        }
        g_Wt[idx] = __float2half_rn(v);
    } else if (idx < 524288 + 65536) {        // g_WlT[n][k] = Wlin[k][n]
        int i2 = idx - 524288;
        int n = i2 >> 8, k = i2 & 255;
        g_WlT[i2] = __float2half_rn(Wlin[k * 256 + n]);
    } else if (idx < 524288 + 65536 + 1024) { // g_bias
        int j = idx - 524288 - 65536;
        int g = j >> 8, jj = j & 255;
        const float* bth = (g == 0) ? bthi : (g == 1) ? bthf : (g == 2) ? bthc : btho;
        const float* bb  = (g == 0) ? bi   : (g == 1) ? bf   : (g == 2) ? bc   : bo;
        g_bias[j] = bth[jj] + bb[jj];
    }
}

// ---------------------------------------------------------------------------
// Gates from fp16 P: 8 columns per thread for MLP.
// ---------------------------------------------------------------------------
__global__ void gates_kernel(const float* __restrict__ c_in,
                             const float* __restrict__ wci,
                             const float* __restrict__ wcf,
                             const float* __restrict__ wco,
                             float* __restrict__ h_out,
                             float* __restrict__ c_out)
{
    int u = blockIdx.x * blockDim.x + threadIdx.x;   // NNODES*32
    if (u >= NNODES * 32) return;
    int n = u >> 5;
    int j = (u & 31) << 3;
    const __half* P = g_P + (size_t)n * 1024;

    uint4 vi = *(const uint4*)(P + j);
    uint4 vf = *(const uint4*)(P + 256 + j);
    uint4 vc = *(const uint4*)(P + 512 + j);
    uint4 vo = *(const uint4*)(P + 768 + j);
    float4 c0 = *(const float4*)(c_in + (size_t)n * 256 + j);
    float4 c1 = *(const float4*)(c_in + (size_t)n * 256 + j + 4);
    float4 wi0 = *(const float4*)(wci + j), wi1 = *(const float4*)(wci + j + 4);
    float4 wf0 = *(const float4*)(wcf + j), wf1 = *(const float4*)(wcf + j + 4);
    float4 wo0 = *(const float4*)(wco + j), wo1 = *(const float4*)(wco + j + 4);

    float pi[8], pf[8], pc[8], po[8];
    {
        const uint32_t* a = &vi.x;
        const uint32_t* b = &vf.x;
        const uint32_t* cc = &vc.x;
        const uint32_t* d = &vo.x;
#pragma unroll
        for (int q = 0; q < 4; ++q) {
            float2 t;
            t = __half22float2(*(const __half2*)&a[q]);  pi[2*q] = t.x; pi[2*q+1] = t.y;
            t = __half22float2(*(const __half2*)&b[q]);  pf[2*q] = t.x; pf[2*q+1] = t.y;
            t = __half22float2(*(const __half2*)&cc[q]); pc[2*q] = t.x; pc[2*q+1] = t.y;
            t = __half22float2(*(const __half2*)&d[q]);  po[2*q] = t.x; po[2*q+1] = t.y;
        }
    }
    float cv[8]  = {c0.x, c0.y, c0.z, c0.w, c1.x, c1.y, c1.z, c1.w};
    float wia[8] = {wi0.x, wi0.y, wi0.z, wi0.w, wi1.x, wi1.y, wi1.z, wi1.w};
    float wfa[8] = {wf0.x, wf0.y, wf0.z, wf0.w, wf1.x, wf1.y, wf1.z, wf1.w};
    float woa[8] = {wo0.x, wo0.y, wo0.z, wo0.w, wo1.x, wo1.y, wo1.z, wo1.w};

    float H[8], Cn[8];
#pragma unroll
    for (int e = 0; e < 8; ++e) {
        float I = sigf(pi[e] + wia[e] * cv[e]);
        float F = sigf(pf[e] + wfa[e] * cv[e]);
        float T = tanf_(pc[e]);
        Cn[e] = F * cv[e] + I * T;
        float O = sigf(po[e] + woa[e] * Cn[e]);
        H[e] = O * tanf_(Cn[e]);
    }

    size_t off = (size_t)n * 256 + j;
    *(float4*)(h_out + off)     = make_float4(H[0], H[1], H[2], H[3]);
    *(float4*)(h_out + off + 4) = make_float4(H[4], H[5], H[6], H[7]);
    *(float4*)(c_out + off)     = make_float4(Cn[0], Cn[1], Cn[2], Cn[3]);
    *(float4*)(c_out + off + 4) = make_float4(Cn[4], Cn[5], Cn[6], Cn[7]);

    uint4 rv;
    __half2 r01 = __floats2half2_rn(fmaxf(H[0], 0.f), fmaxf(H[1], 0.f));
    __half2 r23 = __floats2half2_rn(fmaxf(H[2], 0.f), fmaxf(H[3], 0.f));
    __half2 r45 = __floats2half2_rn(fmaxf(H[4], 0.f), fmaxf(H[5], 0.f));
    __half2 r67 = __floats2half2_rn(fmaxf(H[6], 0.f), fmaxf(H[7], 0.f));
    rv.x = *(uint32_t*)&r01; rv.y = *(uint32_t*)&r23;
    rv.z = *(uint32_t*)&r45; rv.w = *(uint32_t*)&r67;
    *(uint4*)(g_R + off) = rv;
}

// ---------------------------------------------------------------------------
extern "C" void kernel_launch(void* const* d_in, const int* in_sizes, int n_in,
                              void* d_out, int out_size)
{
    const float* x    = (const float*)d_in[0];
    // d_in[1] edge_index, d_in[2] edge_weight -> unused (K=1 ChebConv)
    const float* h    = (const float*)d_in[3];
    const float* c    = (const float*)d_in[4];
    const float* Wi   = (const float*)d_in[5];
    const float* Wf   = (const float*)d_in[6];
    const float* Wc   = (const float*)d_in[7];
    const float* Wo   = (const float*)d_in[8];
    const float* Ti   = (const float*)d_in[9];
    const float* Tf   = (const float*)d_in[10];
    const float* Tc   = (const float*)d_in[11];
    const float* To   = (const float*)d_in[12];
    const float* bthi = (const float*)d_in[13];
    const float* bthf = (const float*)d_in[14];
    const float* bthc = (const float*)d_in[15];
    const float* btho = (const float*)d_in[16];
    const float* wci  = (const float*)d_in[17];
    const float* wcf  = (const float*)d_in[18];
    const float* wco  = (const float*)d_in[19];
    const float* bi   = (const float*)d_in[20];
    const float* bf   = (const float*)d_in[21];
    const float* bc   = (const float*)d_in[22];
    const float* bo   = (const float*)d_in[23];
    const float* Wlin = (const float*)d_in[24];
    const float* blin = (const float*)d_in[25];
    float* out = (float*)d_out;

    float *pBias;
    __half *pA16, *pP, *pWt, *pWlT, *pR;
    cudaGetSymbolAddress((void**)&pBias, g_bias);
    cudaGetSymbolAddress((void**)&pA16, g_A16);
    cudaGetSymbolAddress((void**)&pP, g_P);
    cudaGetSymbolAddress((void**)&pWt, g_Wt);
    cudaGetSymbolAddress((void**)&pWlT, g_WlT);
    cudaGetSymbolAddress((void**)&pR, g_R);

    cudaFuncSetAttribute(hmma_gemm<true>,
                         cudaFuncAttributeMaxDynamicSharedMemorySize, SMEM_DYN);
    cudaFuncSetAttribute(hmma_gemm<false>,
                         cudaFuncAttributeMaxDynamicSharedMemorySize, SMEM_DYN);

    // 1) pack weights/bias to fp16
    pack_kernel<<<(524288 + 65536 + 1024 + 255) / 256, 256>>>(
        Wi, Wf, Wc, Wo, Ti, Tf, Tc, To,
        bthi, bthf, bthc, btho, bi, bf, bc, bo, Wlin);

    // 2) A16 = fp16([x|h])
    prep_a16<<<(NNODES * 64 + 255) / 256, 256>>>(x, h);

    // 3) GEMM1: P = A16 @ Wt^T + bias  (fp16 out)  grid (1024/256, ceil(M/128))
    hmma_gemm<true><<<dim3(4, (NNODES + 127) / 128), 256, SMEM_DYN>>>(
        pA16, pWt, pP, pBias, NNODES, 1024, 512);

    // 4) gates -> h0, c0, R
    const size_t elems = (size_t)NNODES * 256;
    gates_kernel<<<(NNODES * 32 + 255) / 256, 256>>>(
        c, wci, wcf, wco, out + elems, out + 2 * elems);

    // 5) GEMM2: out = R @ WlinT^T + b_lin  (fp32 out)
    hmma_gemm<false><<<dim3(1, (NNODES + 127) / 128), 256, SMEM_DYN>>>(
        pR, pWlT, out, blin, NNODES, 256, 256);
}